// round 3
// baseline (speedup 1.0000x reference)
#include <cuda_runtime.h>
#include <cstdint>

// Fused QKV projection + RoPE + (B,H,S,D) transpose.
// C[16384 x 6144] = X[16384 x 4096] @ [Wq;Wk;Wv]^T, tf32 legacy mma.sync path.
// BM=128 BN=128 BK=32, 256 threads (warp grid 4m x 2n, warp tile 32x64).

namespace {
constexpr int BM = 128, BN = 128, BK = 32;
constexpr int STRIDE = 36;                  // 32-bit words per smem row (conflict-free)
constexpr int TILE_WORDS = BM * STRIDE;     // 4608
constexpr int SMEM_BYTES = 4 * TILE_WORDS * 4;  // A0,A1,B0,B1 = 73728 B
}

__device__ __forceinline__ uint32_t f2tf(float f) {
    uint32_t r; asm("cvt.rna.tf32.f32 %0, %1;" : "=r"(r) : "f"(f)); return r;
}

__global__ void __launch_bounds__(256) qkv_rope_tf32_kernel(
    const float* __restrict__ X, const float* __restrict__ Wq,
    const float* __restrict__ Wk, const float* __restrict__ Wv,
    const float* __restrict__ Ct, const float* __restrict__ St,
    float* __restrict__ Out)
{
    extern __shared__ uint32_t smem[];
    uint32_t* As = smem;                    // 2 stages of A
    uint32_t* Bs = smem + 2 * TILE_WORDS;   // 2 stages of B

    const int tid  = threadIdx.x;
    const int lane = tid & 31;
    const int warp = tid >> 5;
    const int g  = lane >> 2;   // mma group id (row)
    const int tg = lane & 3;    // thread-in-group (k / col pair)
    const int wm = warp & 3;    // warp row 0..3  (32 rows each)
    const int wn = warp >> 2;   // warp col 0..1  (64 cols each)

    const int m0 = blockIdx.y * BM;
    const int n0 = blockIdx.x * BN;

    // Select weight panel: concatenated N = [q:4096 | k:1024 | v:1024]
    const float* Bg;
    if (n0 < 4096)      Bg = Wq + (size_t)n0 * 4096;
    else if (n0 < 5120) Bg = Wk + (size_t)(n0 - 4096) * 4096;
    else                Bg = Wv + (size_t)(n0 - 5120) * 4096;
    const float* Ag = X + (size_t)m0 * 4096;

    // Global->smem mapping: each thread owns 4 rows x one float4 per tile
    const int lrow = tid >> 3;          // 0..31
    const int lcol = (tid & 7) << 2;    // 0,4,...,28

    float4 ra[4], rb[4];

    auto ldg_tile = [&](int kt) {
        const float* a = Ag + kt * BK + lcol;
        const float* b = Bg + kt * BK + lcol;
        #pragma unroll
        for (int i = 0; i < 4; ++i) {
            size_t off = (size_t)(lrow + i * 32) * 4096;
            ra[i] = *reinterpret_cast<const float4*>(a + off);
            rb[i] = *reinterpret_cast<const float4*>(b + off);
        }
    };
    auto sts_tile = [&](int stage) {
        uint32_t* ad = As + stage * TILE_WORDS;
        uint32_t* bd = Bs + stage * TILE_WORDS;
        #pragma unroll
        for (int i = 0; i < 4; ++i) {
            int o = (lrow + i * 32) * STRIDE + lcol;
            uint4 av = make_uint4(f2tf(ra[i].x), f2tf(ra[i].y), f2tf(ra[i].z), f2tf(ra[i].w));
            uint4 bv = make_uint4(f2tf(rb[i].x), f2tf(rb[i].y), f2tf(rb[i].z), f2tf(rb[i].w));
            *reinterpret_cast<uint4*>(ad + o) = av;
            *reinterpret_cast<uint4*>(bd + o) = bv;
        }
    };

    float acc[2][8][4];
    #pragma unroll
    for (int i = 0; i < 2; ++i)
        #pragma unroll
        for (int j = 0; j < 8; ++j)
            #pragma unroll
            for (int c = 0; c < 4; ++c) acc[i][j][c] = 0.f;

    constexpr int NK = 4096 / BK;   // 128 k-tiles

    ldg_tile(0);
    sts_tile(0);
    __syncthreads();

    for (int kt = 0; kt < NK; ++kt) {
        const int stage = kt & 1;
        if (kt + 1 < NK) ldg_tile(kt + 1);   // overlap next LDG with mma

        const uint32_t* At = As + stage * TILE_WORDS + (wm * 32) * STRIDE;
        const uint32_t* Bt = Bs + stage * TILE_WORDS + (wn * 64) * STRIDE;
        #pragma unroll
        for (int k8 = 0; k8 < BK / 8; ++k8) {
            const int kc = k8 * 8 + tg;
            uint32_t af[2][4];
            #pragma unroll
            for (int mt = 0; mt < 2; ++mt) {
                const uint32_t* p = At + (mt * 16 + g) * STRIDE + kc;
                af[mt][0] = p[0];
                af[mt][1] = p[8 * STRIDE];
                af[mt][2] = p[4];
                af[mt][3] = p[8 * STRIDE + 4];
            }
            #pragma unroll
            for (int nt = 0; nt < 8; ++nt) {
                const uint32_t* p = Bt + (nt * 8 + g) * STRIDE + kc;
                const uint32_t b0 = p[0], b1 = p[4];
                #pragma unroll
                for (int mt = 0; mt < 2; ++mt) {
                    float* c = acc[mt][nt];
                    asm volatile(
                        "mma.sync.aligned.m16n8k8.row.col.f32.tf32.tf32.f32 "
                        "{%0,%1,%2,%3}, {%4,%5,%6,%7}, {%8,%9}, {%0,%1,%2,%3};\n"
                        : "+f"(c[0]), "+f"(c[1]), "+f"(c[2]), "+f"(c[3])
                        : "r"(af[mt][0]), "r"(af[mt][1]), "r"(af[mt][2]), "r"(af[mt][3]),
                          "r"(b0), "r"(b1));
                }
            }
        }
        if (kt + 1 < NK) sts_tile(stage ^ 1);
        __syncthreads();
    }

    // ---- Epilogue: RoPE (q,k) + transpose to (B,H,S,D), concatenated [q|k|v] ----
    const bool isv = (n0 >= 5120);
    size_t base; int H, h;
    if (n0 < 4096)      { base = 0ull;                       H = 32; h = n0 >> 7; }
    else if (n0 < 5120) { base = 67108864ull;                H = 8;  h = (n0 - 4096) >> 7; }
    else                { base = 67108864ull + 16777216ull;  H = 8;  h = (n0 - 5120) >> 7; }

    #pragma unroll
    for (int mt = 0; mt < 2; ++mt) {
        #pragma unroll
        for (int rh = 0; rh < 2; ++rh) {
            const int m = m0 + wm * 32 + mt * 16 + g + rh * 8;
            const int b = m >> 12;       // batch
            const int s = m & 4095;      // sequence position
            float* orow = Out + base + (((size_t)(b * H + h) * 4096 + (size_t)s) << 7);
            const float* cr = Ct + (size_t)s * 64;
            const float* sr = St + (size_t)s * 64;
            #pragma unroll
            for (int nt = 0; nt < 8; ++nt) {
                const int d = wn * 64 + nt * 8 + 2 * tg;   // even head-dim index
                float v0 = acc[mt][nt][rh * 2 + 0];
                float v1 = acc[mt][nt][rh * 2 + 1];
                if (!isv) {
                    const float cv = cr[d >> 1];
                    const float sv = sr[d >> 1];
                    const float t0 = v0 * cv - v1 * sv;
                    const float t1 = v0 * sv + v1 * cv;
                    v0 = t0; v1 = t1;
                }
                *reinterpret_cast<float2*>(orow + d) = make_float2(v0, v1);
            }
        }
    }
}

extern "C" void kernel_launch(void* const* d_in, const int* in_sizes, int n_in,
                              void* d_out, int out_size) {
    (void)in_sizes; (void)n_in; (void)out_size;
    const float* x  = (const float*)d_in[0];
    const float* wq = (const float*)d_in[1];
    const float* wk = (const float*)d_in[2];
    const float* wv = (const float*)d_in[3];
    const float* ct = (const float*)d_in[4];
    const float* st = (const float*)d_in[5];
    float* out = (float*)d_out;

    cudaFuncSetAttribute(qkv_rope_tf32_kernel,
                         cudaFuncAttributeMaxDynamicSharedMemorySize, SMEM_BYTES);
    dim3 grid(48, 128);   // 48 n-tiles (6144/128), 128 m-tiles (16384/128)
    qkv_rope_tf32_kernel<<<grid, 256, SMEM_BYTES>>>(x, wq, wk, wv, ct, st, out);
}

// round 7
// speedup vs baseline: 1.9823x; 1.9823x over previous
#include <cuda_runtime.h>
#include <cstdint>

// Fused QKV projection + RoPE + (B,H,S,D) transpose.
// tf32 mma.sync + ldmatrix fragments, 2 CTAs/SM.
// BM=128 BN=128 BK=32, 256 threads (warp grid 4m x 2n, warp tile 32x64).

namespace {
constexpr int NK = 128;                   // 4096 / 32 k-tiles
constexpr int ROWB = 144;                 // bytes per smem row (36 words, padded)
constexpr int A_TILE = 128 * ROWB;        // 18432
constexpr int STAGE = 2 * A_TILE;         // A + B = 36864
constexpr int SMEM_BYTES = 2 * STAGE;     // 73728
}

__device__ __forceinline__ uint32_t cvta_smem(const void* p) {
    uint32_t a;
    asm("{ .reg .u64 t; cvta.to.shared.u64 t, %1; cvt.u32.u64 %0, t; }"
        : "=r"(a) : "l"(p));
    return a;
}
__device__ __forceinline__ uint32_t f2tf(float f) {
    uint32_t r; asm("cvt.rna.tf32.f32 %0, %1;" : "=r"(r) : "f"(f)); return r;
}
__device__ __forceinline__ void ldsm4(uint32_t& r0, uint32_t& r1,
                                      uint32_t& r2, uint32_t& r3, uint32_t addr) {
    asm volatile("ldmatrix.sync.aligned.m8n8.x4.shared.b16 {%0,%1,%2,%3}, [%4];"
                 : "=r"(r0), "=r"(r1), "=r"(r2), "=r"(r3) : "r"(addr));
}
__device__ __forceinline__ void mma8(float* c, const uint32_t* a,
                                     uint32_t b0, uint32_t b1) {
    asm volatile(
        "mma.sync.aligned.m16n8k8.row.col.f32.tf32.tf32.f32 "
        "{%0,%1,%2,%3}, {%4,%5,%6,%7}, {%8,%9}, {%0,%1,%2,%3};\n"
        : "+f"(c[0]), "+f"(c[1]), "+f"(c[2]), "+f"(c[3])
        : "r"(a[0]), "r"(a[1]), "r"(a[2]), "r"(a[3]), "r"(b0), "r"(b1));
}

__global__ void __launch_bounds__(256, 2) qkv_rope_tf32_ldsm(
    const float* __restrict__ X, const float* __restrict__ Wq,
    const float* __restrict__ Wk, const float* __restrict__ Wv,
    const float* __restrict__ Ct, const float* __restrict__ St,
    float* __restrict__ Out)
{
    extern __shared__ __align__(1024) uint8_t smem[];
    const uint32_t sbase = cvta_smem(smem);

    const int tid  = threadIdx.x;
    const int lane = tid & 31;
    const int warp = tid >> 5;
    const int g  = lane >> 2;
    const int tg = lane & 3;
    const int wm = warp & 3;    // warp row (32 m each)
    const int wn = warp >> 2;   // warp col (64 n each)

    const int m0 = blockIdx.y * 128;
    const int n0 = blockIdx.x * 128;

    const float* Bpanel;
    if (n0 < 4096)      Bpanel = Wq + (size_t)n0 * 4096;
    else if (n0 < 5120) Bpanel = Wk + (size_t)(n0 - 4096) * 4096;
    else                Bpanel = Wv + (size_t)(n0 - 5120) * 4096;
    const float* Ag = X + (size_t)m0 * 4096;

    // producer mapping: each thread 4 A rows + 4 B rows, one float4 per row
    const int prow = tid >> 3;          // 0..31
    const int pcol = tid & 7;           // float4 index in BK=32

    float4 ra[4], rb[4];
    auto ldg_tile = [&](int kt) {
        const float* a = Ag + kt * 32 + pcol * 4;
        const float* b = Bpanel + kt * 32 + pcol * 4;
        #pragma unroll
        for (int i = 0; i < 4; ++i) {
            size_t off = (size_t)(prow + i * 32) * 4096;
            ra[i] = *reinterpret_cast<const float4*>(a + off);
            rb[i] = *reinterpret_cast<const float4*>(b + off);
        }
    };
    auto sts_tile = [&](int s) {
        const uint32_t ab = sbase + s * STAGE + prow * ROWB + pcol * 16;
        #pragma unroll
        for (int i = 0; i < 4; ++i) {
            const uint32_t o = ab + i * 32 * ROWB;
            asm volatile("st.shared.v4.b32 [%0], {%1,%2,%3,%4};" :: "r"(o),
                "r"(f2tf(ra[i].x)), "r"(f2tf(ra[i].y)), "r"(f2tf(ra[i].z)), "r"(f2tf(ra[i].w)));
            asm volatile("st.shared.v4.b32 [%0], {%1,%2,%3,%4};" :: "r"(o + A_TILE),
                "r"(f2tf(rb[i].x)), "r"(f2tf(rb[i].y)), "r"(f2tf(rb[i].z)), "r"(f2tf(rb[i].w)));
        }
    };

    // ldmatrix base offsets (within one stage)
    const int am = lane >> 3;           // matrix index 0..3
    const int ar = lane & 7;            // row within matrix
    uint32_t aoff[2], boff[4];
    #pragma unroll
    for (int mt = 0; mt < 2; ++mt)
        aoff[mt] = (uint32_t)((wm * 32 + mt * 16 + (am & 1) * 8 + ar) * ROWB
                              + (am >> 1) * 16);
    #pragma unroll
    for (int p = 0; p < 4; ++p)
        boff[p] = (uint32_t)(A_TILE + (wn * 64 + p * 16 + (am >> 1) * 8 + ar) * ROWB
                             + (am & 1) * 16);

    float acc[2][8][4];
    #pragma unroll
    for (int i = 0; i < 2; ++i)
        #pragma unroll
        for (int j = 0; j < 8; ++j)
            #pragma unroll
            for (int c = 0; c < 4; ++c) acc[i][j][c] = 0.f;

    ldg_tile(0);
    sts_tile(0);
    __syncthreads();

    for (int kt = 0; kt < NK; ++kt) {
        const int stage = kt & 1;
        if (kt + 1 < NK) ldg_tile(kt + 1);

        const uint32_t sb = sbase + stage * STAGE;
        #pragma unroll
        for (int k8 = 0; k8 < 4; ++k8) {
            uint32_t af[2][4];
            ldsm4(af[0][0], af[0][1], af[0][2], af[0][3], sb + aoff[0] + k8 * 32);
            ldsm4(af[1][0], af[1][1], af[1][2], af[1][3], sb + aoff[1] + k8 * 32);
            #pragma unroll
            for (int p = 0; p < 4; ++p) {
                uint32_t b0, b1, b2, b3;
                ldsm4(b0, b1, b2, b3, sb + boff[p] + k8 * 32);
                #pragma unroll
                for (int mt = 0; mt < 2; ++mt) {
                    mma8(acc[mt][2 * p],     af[mt], b0, b1);
                    mma8(acc[mt][2 * p + 1], af[mt], b2, b3);
                }
            }
        }
        if (kt + 1 < NK) sts_tile(stage ^ 1);
        __syncthreads();
    }

    // ---- Epilogue: RoPE (q,k) + transpose to (B,H,S,D), concatenated [q|k|v] ----
    const bool isv = (n0 >= 5120);
    size_t base; int H, h;
    if (n0 < 4096)      { base = 0ull;                      H = 32; h = n0 >> 7; }
    else if (n0 < 5120) { base = 67108864ull;               H = 8;  h = (n0 - 4096) >> 7; }
    else                { base = 67108864ull + 16777216ull; H = 8;  h = (n0 - 5120) >> 7; }

    #pragma unroll
    for (int mt = 0; mt < 2; ++mt) {
        #pragma unroll
        for (int rh = 0; rh < 2; ++rh) {
            const int m = m0 + wm * 32 + mt * 16 + g + rh * 8;
            const int b = m >> 12;       // batch
            const int s = m & 4095;      // sequence position
            float* orow = Out + base + (((size_t)(b * H + h) * 4096 + (size_t)s) << 7);
            const float* cr = Ct + (size_t)s * 64;
            const float* sr = St + (size_t)s * 64;
            #pragma unroll
            for (int nt = 0; nt < 8; ++nt) {
                const int d = wn * 64 + nt * 8 + 2 * tg;   // even head-dim index
                float v0 = acc[mt][nt][rh * 2 + 0];
                float v1 = acc[mt][nt][rh * 2 + 1];
                if (!isv) {
                    const float cv = cr[d >> 1];
                    const float sv = sr[d >> 1];
                    const float t0 = v0 * cv - v1 * sv;
                    const float t1 = v0 * sv + v1 * cv;
                    v0 = t0; v1 = t1;
                }
                *reinterpret_cast<float2*>(orow + d) = make_float2(v0, v1);
            }
        }
    }
}

extern "C" void kernel_launch(void* const* d_in, const int* in_sizes, int n_in,
                              void* d_out, int out_size) {
    (void)in_sizes; (void)n_in; (void)out_size;
    const float* x  = (const float*)d_in[0];
    const float* wq = (const float*)d_in[1];
    const float* wk = (const float*)d_in[2];
    const float* wv = (const float*)d_in[3];
    const float* ct = (const float*)d_in[4];
    const float* st = (const float*)d_in[5];
    float* out = (float*)d_out;

    cudaFuncSetAttribute(qkv_rope_tf32_ldsm,
                         cudaFuncAttributeMaxDynamicSharedMemorySize, SMEM_BYTES);
    dim3 grid(48, 128);   // 48 n-tiles, 128 m-tiles
    qkv_rope_tf32_ldsm<<<grid, 256, SMEM_BYTES>>>(x, wq, wk, wv, ct, st, out);
}